// round 14
// baseline (speedup 1.0000x reference)
#include <cuda_runtime.h>
#include <cstdint>

// x: (128, 1, 28, 28) f32  -> out: (128, 785, 28, 28) f32
// out[b,0,:]   = new_pv(x[b])
// out[b,1+i,:] = new_e(x[b,i]) at flat pos i, else 0
static constexpr unsigned B     = 128;
static constexpr unsigned HW    = 784;               // floats per channel
static constexpr unsigned HW8   = 98;                // 32B chunks per channel
static constexpr unsigned CPB4  = 785u * 196u;       // float4 per batch = 153,860
static constexpr unsigned CPB8  = 785u * 98u;        // 32B chunks per batch = 76,930
static constexpr unsigned F8_PER_BLOCK = 2048;       // 64KB contiguous per block
static constexpr unsigned ITERS = 8;                 // 2048 / 256
static constexpr unsigned STEP  = 256;               // threads per block

__device__ __forceinline__ float pv_map(float pv) {
    const float eps = 0.1f;
    bool low  = pv < eps;
    bool high = pv > 1.0f - eps;
    return low  ? (pv + eps) * 0.5f
         : high ? (pv + (1.0f - eps)) * 0.5f
         :        pv;
}

__device__ __forceinline__ float e_map(float pv) {
    const float eps = 0.1f;
    bool low  = pv < eps;
    bool high = pv > 1.0f - eps;
    return low  ? (eps + pv) * 0.5f
         : high ? ((1.0f - pv) + eps) * 0.5f
         :        eps;
}

// Blackwell 256-bit store: one STG.256 = 32B, warp covers 1024B contiguous.
__device__ __forceinline__ void st256(float4* p, float4 a, float4 b) {
    asm volatile(
        "st.global.v8.b32 [%0], {%1, %2, %3, %4, %5, %6, %7, %8};"
        :: "l"(p),
           "r"(__float_as_uint(a.x)), "r"(__float_as_uint(a.y)),
           "r"(__float_as_uint(a.z)), "r"(__float_as_uint(a.w)),
           "r"(__float_as_uint(b.x)), "r"(__float_as_uint(b.y)),
           "r"(__float_as_uint(b.z)), "r"(__float_as_uint(b.w))
        : "memory");
}

// Warp-coalesced fused kernel, 256-bit stores. Thread stores 8 x 32B chunks at
// 8KB (256-chunk) stride. 98 chunks/channel => a chunk never crosses a channel
// boundary. Only integer division is in the prologue.
__global__ void fused_kernel(const float* __restrict__ x,
                             float4* __restrict__ out) {
    const unsigned b = blockIdx.y;
    unsigned j8 = blockIdx.x * F8_PER_BLOCK + threadIdx.x;  // 32B-chunk idx in batch

    const float* xb = x + b * HW;
    float4* ob = out + (unsigned long long)b * CPB4;

    // Prologue: one division, then incremental updates.
    unsigned c  = j8 / HW8;               // channel
    unsigned r8 = j8 - c * HW8;           // chunk offset within channel

    #pragma unroll
    for (unsigned j = 0; j < ITERS; j++) {
        if (j8 < CPB8) {
            unsigned d = c - 1u - 8u * r8;     // diag offset in 8-float window

            float4 va = make_float4(0.f, 0.f, 0.f, 0.f);
            float4 vb = make_float4(0.f, 0.f, 0.f, 0.f);
            if (c == 0u) {
                // channel 0: pv map of 8 contiguous inputs (block x==0 only)
                const float4* xs = reinterpret_cast<const float4*>(xb) + 2u * r8;
                float4 x0 = xs[0], x1 = xs[1];
                va.x = pv_map(x0.x); va.y = pv_map(x0.y);
                va.z = pv_map(x0.z); va.w = pv_map(x0.w);
                vb.x = pv_map(x1.x); vb.y = pv_map(x1.y);
                vb.z = pv_map(x1.z); vb.w = pv_map(x1.w);
            } else if (d < 8u) {
                // diagonal element lands in this 32B chunk (1 in 98)
                float ev = e_map(xb[c - 1u]);
                va.x = (d == 0u) ? ev : 0.f;
                va.y = (d == 1u) ? ev : 0.f;
                va.z = (d == 2u) ? ev : 0.f;
                va.w = (d == 3u) ? ev : 0.f;
                vb.x = (d == 4u) ? ev : 0.f;
                vb.y = (d == 5u) ? ev : 0.f;
                vb.z = (d == 6u) ? ev : 0.f;
                vb.w = (d == 7u) ? ev : 0.f;
            }
            st256(ob + 2u * j8, va, vb);
        }
        // Advance by 256 chunks: c += 2, r8 += 60, with at most one wrap.
        j8 += STEP;
        c  += 2u;
        r8 += STEP - 2u * HW8;                 // +60
        if (r8 >= HW8) { r8 -= HW8; c += 1u; }
    }
}

extern "C" void kernel_launch(void* const* d_in, const int* in_sizes, int n_in,
                              void* d_out, int out_size) {
    const float* x = (const float*)d_in[0];
    float4* out = (float4*)d_out;

    const int threads = 256;
    dim3 grid((CPB8 + F8_PER_BLOCK - 1) / F8_PER_BLOCK, B);  // (38, 128)
    fused_kernel<<<grid, threads>>>(x, out);
}

// round 15
// speedup vs baseline: 1.0832x; 1.0832x over previous
#include <cuda_runtime.h>
#include <cstdint>

// x: (128, 1, 28, 28) f32  -> out: (128, 785, 28, 28) f32
// out[b,0,:]   = new_pv(x[b])
// out[b,1+i,:] = new_e(x[b,i]) at flat pos i, else 0
//
// Converged design (R9/R10/R12 family, ~46.3us kernel = ~6.8 TB/s store
// throughput = the path-independent LTS chip cap on sm_100a):
//  - one thread stores 8 float4s at 4KB (256-f4) stride -> every warp STG.128
//    covers a contiguous 512B span (perfect coalescing)
//  - (channel, offset) tracked incrementally; single div in the prologue
//  - __stcs streaming stores (output is write-once, never re-read)
static constexpr unsigned B     = 128;
static constexpr unsigned HW    = 784;               // floats per channel
static constexpr unsigned HW4   = 196;               // float4 per channel
static constexpr unsigned CPB4  = 785u * 196u;       // float4 per batch = 153,860
static constexpr unsigned F4_PER_BLOCK = 2048;       // 32KB contiguous per block
static constexpr unsigned ITERS = 8;                 // 2048 / 256
static constexpr unsigned STEP  = 256;               // threads per block

__device__ __forceinline__ float pv_map(float pv) {
    const float eps = 0.1f;
    bool low  = pv < eps;
    bool high = pv > 1.0f - eps;
    return low  ? (pv + eps) * 0.5f
         : high ? (pv + (1.0f - eps)) * 0.5f
         :        pv;
}

__device__ __forceinline__ float e_map(float pv) {
    const float eps = 0.1f;
    bool low  = pv < eps;
    bool high = pv > 1.0f - eps;
    return low  ? (eps + pv) * 0.5f
         : high ? ((1.0f - pv) + eps) * 0.5f
         :        eps;
}

__global__ void fused_kernel(const float* __restrict__ x,
                             float4* __restrict__ out) {
    const unsigned b = blockIdx.y;
    unsigned j4 = blockIdx.x * F4_PER_BLOCK + threadIdx.x;  // f4 index in batch

    const float* xb = x + b * HW;
    float4* ob = out + (unsigned long long)b * (unsigned long long)CPB4;

    // Prologue: one division, then incremental updates.
    unsigned c  = j4 / HW4;               // channel
    unsigned r4 = j4 - c * HW4;           // f4 offset within channel

    #pragma unroll
    for (unsigned j = 0; j < ITERS; j++) {
        if (j4 < CPB4) {
            unsigned d = c - 1u - 4u * r4;     // diag offset in window (wraps)

            float4 v = make_float4(0.f, 0.f, 0.f, 0.f);
            if (c == 0u) {
                // channel 0: pv map of 4 contiguous inputs (only block x==0)
                float4 xv = reinterpret_cast<const float4*>(xb)[r4];
                v.x = pv_map(xv.x);
                v.y = pv_map(xv.y);
                v.z = pv_map(xv.z);
                v.w = pv_map(xv.w);
            } else if (d < 4u) {
                // diagonal element lands in this float4 (1 in 196)
                float ev = e_map(xb[c - 1u]);
                v.x = (d == 0u) ? ev : 0.f;
                v.y = (d == 1u) ? ev : 0.f;
                v.z = (d == 2u) ? ev : 0.f;
                v.w = (d == 3u) ? ev : 0.f;
            }
            __stcs(ob + j4, v);                // streaming store, evict-first
        }
        // Advance by 256 f4: c += 1, r4 += 60, with at most one wrap.
        j4 += STEP;
        c  += 1u;
        r4 += STEP - HW4;                      // +60
        if (r4 >= HW4) { r4 -= HW4; c += 1u; }
    }
}

extern "C" void kernel_launch(void* const* d_in, const int* in_sizes, int n_in,
                              void* d_out, int out_size) {
    const float* x = (const float*)d_in[0];
    float4* out = (float4*)d_out;

    const int threads = 256;
    dim3 grid((CPB4 + F4_PER_BLOCK - 1) / F4_PER_BLOCK, B);  // (76, 128)
    fused_kernel<<<grid, threads>>>(x, out);
}